// round 15
// baseline (speedup 1.0000x reference)
#include <cuda_runtime.h>
#include <cuda_bf16.h>
#include <cstdint>

#define NN 16384
#define EE 393216
#define EF (EE + NN)      // 409600 edges incl. self loops
#define GG 256
#define HIDN 128
#define NHEAD 4
#define HC 32
#define NLAY 8
#define NDIM 21
#define EDIM 6

// ---------------- scratch (device globals; no allocation allowed) ----------
__device__ float g_bufA[NN * HIDN];
__device__ float g_bufB[NN * HIDN];
__device__ float g_xl[NN * HIDN];
__device__ float g_xr[NN * HIDN];
__device__ float g_conv[NN * HIDN];
__device__ int   g_deg[NN];
__device__ int   g_rowoff[NN + 1];
__device__ int   g_rank[EE];
__device__ int   g_bsum[64];
__device__ int   g_boff[64];
__device__ int   g_dhist[128];
__device__ int   g_dbase[128];
__device__ int   g_rank2[NN];
__device__ int   g_nodeorder[NN];
__device__ float g_erec[(size_t)EF * 8];   // [src_bits, ea0..ea5, pad] per edge
__device__ float g_stats[NLAY * 2 * HIDN];
__device__ float g_pooled[GG * HIDN];
__device__ float g_gcnt[GG];
__device__ __nv_bfloat16 g_w_hi[NLAY * 2 * HIDN * HIDN];
__device__ __nv_bfloat16 g_w_lo[NLAY * 2 * HIDN * HIDN];

// ---------------- helpers ------------------------------------------------------
__device__ __forceinline__ void bf_split(float f, __nv_bfloat16& hi, __nv_bfloat16& lo) {
    hi = __float2bfloat16(f);
    lo = __float2bfloat16(f - __bfloat162float(hi));
}
__device__ __forceinline__ uint32_t bf_pack(__nv_bfloat16 a, __nv_bfloat16 b) {
    __nv_bfloat162 p(a, b);
    return *(uint32_t*)&p;
}
__device__ __forceinline__ void mma_bf16(float* d, uint32_t a0, uint32_t a1,
                                         uint32_t a2, uint32_t a3,
                                         uint32_t b0, uint32_t b1) {
    asm volatile(
        "mma.sync.aligned.m16n8k16.row.col.f32.bf16.bf16.f32 "
        "{%0,%1,%2,%3}, {%4,%5,%6,%7}, {%8,%9}, {%0,%1,%2,%3};"
        : "+f"(d[0]), "+f"(d[1]), "+f"(d[2]), "+f"(d[3])
        : "r"(a0), "r"(a1), "r"(a2), "r"(a3), "r"(b0), "r"(b1));
}

// ---------------- init ------------------------------------------------------
__global__ void k_init() {
    int i = blockIdx.x * blockDim.x + threadIdx.x;
    int stride = gridDim.x * blockDim.x;
    for (int j = i; j < NN; j += stride) g_deg[j] = 0;
    for (int j = i; j < 128; j += stride) g_dhist[j] = 0;
    for (int j = i; j < NLAY * 2 * HIDN; j += stride) g_stats[j] = 0.f;
    for (int j = i; j < GG * HIDN; j += stride) g_pooled[j] = 0.f;
    for (int j = i; j < GG; j += stride) g_gcnt[j] = 0.f;
}

// ---------------- weight split + transpose (once per launch) ----------------
__global__ void k_wsplit(const float* __restrict__ Wl, const float* __restrict__ Wr) {
    int idx = blockIdx.x * blockDim.x + threadIdx.x;
    if (idx >= NLAY * 2 * HIDN * HIDN) return;
    int l2 = idx >> 14;
    int rem = idx & 16383;
    int n = rem >> 7;
    int k = rem & 127;
    int l = l2 >> 1, side = l2 & 1;
    const float* W = (side ? Wr : Wl) + (size_t)l * HIDN * HIDN;
    float v = W[k * HIDN + n];
    __nv_bfloat16 hi, lo;
    bf_split(v, hi, lo);
    g_w_hi[idx] = hi;
    g_w_lo[idx] = lo;
}

// ---------------- degree count + within-dst rank -----------------------------
__global__ void k_deg(const int* __restrict__ ei) {
    int e = blockIdx.x * blockDim.x + threadIdx.x;
    if (e >= EE) return;
    g_rank[e] = atomicAdd(&g_deg[ei[EE + e]], 1);
}

// ---------------- scanA: rowoff block-scan + degree histogram (fused) -------
__global__ void k_scanA() {      // 64 blocks x 256 threads, 1 node each
    __shared__ int wsums[8];
    int n = blockIdx.x * 256 + threadIdx.x;
    int lane = threadIdx.x & 31, w = threadIdx.x >> 5;
    int d = g_deg[n];
    g_rank2[n] = atomicAdd(&g_dhist[min(d, 127)], 1);
    int v = d + 1;
    int x = v;
#pragma unroll
    for (int off = 1; off < 32; off <<= 1) {
        int u = __shfl_up_sync(0xffffffffu, x, off);
        if (lane >= off) x += u;
    }
    if (lane == 31) wsums[w] = x;
    __syncthreads();
    if (w == 0) {
        int s = (lane < 8) ? wsums[lane] : 0;
#pragma unroll
        for (int off = 1; off < 8; off <<= 1) {
            int u = __shfl_up_sync(0xffffffffu, s, off);
            if (lane >= off) s += u;
        }
        if (lane < 8) wsums[lane] = s;
    }
    __syncthreads();
    int excl = x - v + (w ? wsums[w - 1] : 0);
    g_rowoff[n] = excl;
    if (threadIdx.x == 255) g_bsum[blockIdx.x] = excl + v;
}

// ---------------- scanB: block-sum scan (64) + dhist scan (128), one block --
__global__ void k_scanB() {      // 1 block, 192 threads
    __shared__ int ws[2];
    __shared__ int ws2[4];
    int t = threadIdx.x;
    int v = 0, x = 0;
    if (t < 64) {
        int lane = t & 31, w = t >> 5;
        v = g_bsum[t];
        x = v;
#pragma unroll
        for (int off = 1; off < 32; off <<= 1) {
            int u = __shfl_up_sync(0xffffffffu, x, off);
            if (lane >= off) x += u;
        }
        if (lane == 31) ws[w] = x;
    } else {
        int t2 = t - 64;
        int lane = t2 & 31, w2 = t2 >> 5;
        v = g_dhist[t2];
        x = v;
#pragma unroll
        for (int off = 1; off < 32; off <<= 1) {
            int u = __shfl_up_sync(0xffffffffu, x, off);
            if (lane >= off) x += u;
        }
        if (lane == 31) ws2[w2] = x;
    }
    __syncthreads();
    if (t < 64) {
        int w = t >> 5;
        int excl = x - v + (w ? ws[0] : 0);
        g_boff[t] = excl;
        if (t == 63) g_rowoff[NN] = excl + v;
    } else {
        int t2 = t - 64;
        int w2 = t2 >> 5;
        int base = 0;
#pragma unroll
        for (int i = 0; i < 4; i++) if (i < w2) base += ws2[i];
        g_dbase[t2] = x - v + base;
    }
}

// ---------------- scanC: rowoff fixup + degree-sorted placement (fused) -----
__global__ void k_scanC() {      // 64 blocks x 256
    int n = blockIdx.x * 256 + threadIdx.x;
    g_rowoff[n] += g_boff[blockIdx.x];
    int b = min(g_deg[n], 127);
    g_nodeorder[g_dbase[b] + g_rank2[n]] = n;
}

// ---------------- scatter: self-loop at slot 0, real edges after (no atomic) -
__global__ void k_scatter(const int* __restrict__ ei, const float* __restrict__ ea) {
    int t = blockIdx.x * blockDim.x + threadIdx.x;
    if (t >= EF) return;
    if (t < EE) {
        int s = ei[t], d = ei[EE + t];
        int pos = g_rowoff[d] + 1 + g_rank[t];
        const float2* src = (const float2*)(ea + (size_t)t * EDIM);  // 8B-aligned
        float2 p0 = __ldg(&src[0]), p1 = __ldg(&src[1]), p2 = __ldg(&src[2]);
        float4* dst = (float4*)(g_erec + (size_t)pos * 8);
        dst[0] = make_float4(__int_as_float(s), p0.x, p0.y, p1.x);
        dst[1] = make_float4(p1.y, p2.x, p2.y, 0.f);
    } else {
        int n = t - EE;
        g_erec[(size_t)g_rowoff[n] * 8] = __int_as_float(n);   // self loop src
    }
}

// ---------------- self-loop attr = mean of incoming (warp per node) ---------
__global__ void k_loopattr() {
    int lane = threadIdx.x & 31;
    int n = blockIdx.x * 8 + (threadIdx.x >> 5);
    if (n >= NN) return;
    int beg = g_rowoff[n], end = g_rowoff[n + 1];
    float s0 = 0.f, s1 = 0.f, s2 = 0.f, s3 = 0.f, s4 = 0.f, s5 = 0.f;
    const float4* rec = (const float4*)g_erec;
    for (int j = beg + 1 + lane; j < end; j += 32) {
        float4 A = rec[2 * (size_t)j];
        float4 B = rec[2 * (size_t)j + 1];
        s0 += A.y; s1 += A.z; s2 += A.w;
        s3 += B.x; s4 += B.y; s5 += B.z;
    }
#pragma unroll
    for (int off = 16; off > 0; off >>= 1) {
        s0 += __shfl_xor_sync(0xffffffffu, s0, off);
        s1 += __shfl_xor_sync(0xffffffffu, s1, off);
        s2 += __shfl_xor_sync(0xffffffffu, s2, off);
        s3 += __shfl_xor_sync(0xffffffffu, s3, off);
        s4 += __shfl_xor_sync(0xffffffffu, s4, off);
        s5 += __shfl_xor_sync(0xffffffffu, s5, off);
    }
    if (lane == 0) {
        float inv = 1.0f / fmaxf((float)(end - beg - 1), 1.0f);
        float4* dst = (float4*)(g_erec + (size_t)beg * 8);
        float src = g_erec[(size_t)beg * 8];
        dst[0] = make_float4(src, s0 * inv, s1 * inv, s2 * inv);
        dst[1] = make_float4(s3 * inv, s4 * inv, s5 * inv, 0.f);
    }
}

// ---------------- input projection: h = relu(x @ Win + b_in) ---------------
__global__ void k_ingemm(const float* __restrict__ x, const float* __restrict__ Win,
                         const float* __restrict__ b_in) {
    __shared__ float xs[NDIM];
    int n = blockIdx.x;
    int f = threadIdx.x;
    if (f < NDIM) xs[f] = x[n * NDIM + f];
    __syncthreads();
    float a = b_in[f];
#pragma unroll
    for (int k = 0; k < NDIM; k++) a += xs[k] * Win[k * HIDN + f];
    g_bufA[n * HIDN + f] = fmaxf(a, 0.f);
}

// ---------------- tensor-core dual GEMM with fused BN-apply in A-staging ----
#define GPAD 20
__global__ void __launch_bounds__(256)
k_gemm_bf16(const __nv_bfloat16* __restrict__ whi, const __nv_bfloat16* __restrict__ wlo,
            const float* __restrict__ bl, const float* __restrict__ br,
            const float* __restrict__ conv_src,
            const float* __restrict__ stats,
            const float* __restrict__ gamma_l, const float* __restrict__ beta_l,
            const float* __restrict__ res, float* __restrict__ hout) {
    __shared__ uint32_t sAh[128 * GPAD];
    __shared__ uint32_t sAl[128 * GPAD];
    __shared__ uint32_t sBh[128 * GPAD];
    __shared__ uint32_t sBl[128 * GPAD];
    __shared__ float sa[HIDN], sb[HIDN];

    const float* bias = blockIdx.y ? br : bl;
    float* out        = blockIdx.y ? g_xr : g_xl;
    const uint32_t* Wh  = (const uint32_t*)(whi + (size_t)blockIdx.y * HIDN * HIDN);
    const uint32_t* Wl_ = (const uint32_t*)(wlo + (size_t)blockIdx.y * HIDN * HIDN);

    int t = threadIdx.x;
    if (t < HIDN) {
        float A = 1.f, Bc = 0.f;
        if (gamma_l) {
            const float invN = 1.0f / (float)NN;
            float mean = stats[t] * invN;
            float var = stats[HIDN + t] * invN - mean * mean;
            float istd = rsqrtf(var + 1e-5f);
            A = gamma_l[t] * istd;
            Bc = beta_l[t] - A * mean;
        }
        sa[t] = A; sb[t] = Bc;
    }
    __syncthreads();

    int lane = t & 31;
    int warp = t >> 5;
    int mloc = (warp & 1) * 64;
    int nloc = (warp >> 1) * 32;
    int mtile = blockIdx.x * 128;
    int lq = lane >> 2;
    int lr = lane & 3;
    bool wout = (hout != nullptr) && (blockIdx.y == 0);

    float acc[4][4][4];
#pragma unroll
    for (int mt = 0; mt < 4; mt++)
#pragma unroll
        for (int nt = 0; nt < 4; nt++)
#pragma unroll
            for (int i = 0; i < 4; i++) acc[mt][nt][i] = 0.f;

#pragma unroll
    for (int kc = 0; kc < 4; kc++) {
        int kb = kc * 32;
        int kbase = kc * 16;
#pragma unroll
        for (int it = 0; it < 4; it++) {
            int i4 = it * 256 + t;
            int row = i4 >> 3;
            int c8 = i4 & 7;
            int gcol = kb + c8 * 4;
            size_t gidx = (size_t)(mtile + row) * HIDN + gcol;
            float4 c = *(const float4*)(conv_src + gidx);
            float4 y;
            y.x = sa[gcol] * c.x + sb[gcol];
            y.y = sa[gcol + 1] * c.y + sb[gcol + 1];
            y.z = sa[gcol + 2] * c.z + sb[gcol + 2];
            y.w = sa[gcol + 3] * c.w + sb[gcol + 3];
            if (res) {
                float4 r4 = *(const float4*)(res + gidx);
                y.x += r4.x; y.y += r4.y; y.z += r4.z; y.w += r4.w;
            }
            y.x = fmaxf(y.x, 0.f); y.y = fmaxf(y.y, 0.f);
            y.z = fmaxf(y.z, 0.f); y.w = fmaxf(y.w, 0.f);
            if (wout) *(float4*)(hout + gidx) = y;
            __nv_bfloat16 h0, l0, h1, l1, h2, l2, h3, l3;
            bf_split(y.x, h0, l0); bf_split(y.y, h1, l1);
            bf_split(y.z, h2, l2); bf_split(y.w, h3, l3);
            sAh[row * GPAD + c8 * 2]     = bf_pack(h0, h1);
            sAh[row * GPAD + c8 * 2 + 1] = bf_pack(h2, h3);
            sAl[row * GPAD + c8 * 2]     = bf_pack(l0, l1);
            sAl[row * GPAD + c8 * 2 + 1] = bf_pack(l2, l3);
        }
#pragma unroll
        for (int it = 0; it < 2; it++) {
            int i4 = it * 256 + t;
            int row = i4 >> 2, u = (i4 & 3) << 2;
            *(uint4*)(sBh + row * GPAD + u) =
                *(const uint4*)(Wh + (size_t)row * 64 + kbase + u);
            *(uint4*)(sBl + row * GPAD + u) =
                *(const uint4*)(Wl_ + (size_t)row * 64 + kbase + u);
        }
        __syncthreads();

#pragma unroll
        for (int ks = 0; ks < 2; ks++) {
            int c0 = ks * 8 + lr;
            uint32_t ah[4][4], al[4][4];
#pragma unroll
            for (int mt = 0; mt < 4; mt++) {
                int r0 = (mloc + mt * 16 + lq) * GPAD;
                int r1 = r0 + 8 * GPAD;
                ah[mt][0] = sAh[r0 + c0];
                ah[mt][1] = sAh[r1 + c0];
                ah[mt][2] = sAh[r0 + c0 + 4];
                ah[mt][3] = sAh[r1 + c0 + 4];
                al[mt][0] = sAl[r0 + c0];
                al[mt][1] = sAl[r1 + c0];
                al[mt][2] = sAl[r0 + c0 + 4];
                al[mt][3] = sAl[r1 + c0 + 4];
            }
            uint32_t bh[4][2], blr[4][2];
#pragma unroll
            for (int nt = 0; nt < 4; nt++) {
                int rb = (nloc + nt * 8 + lq) * GPAD;
                bh[nt][0]  = sBh[rb + c0];
                bh[nt][1]  = sBh[rb + c0 + 4];
                blr[nt][0] = sBl[rb + c0];
                blr[nt][1] = sBl[rb + c0 + 4];
            }
#pragma unroll
            for (int mt = 0; mt < 4; mt++)
#pragma unroll
                for (int nt = 0; nt < 4; nt++) {
                    mma_bf16(acc[mt][nt], ah[mt][0], ah[mt][1], ah[mt][2], ah[mt][3],
                             bh[nt][0], bh[nt][1]);
                    mma_bf16(acc[mt][nt], ah[mt][0], ah[mt][1], ah[mt][2], ah[mt][3],
                             blr[nt][0], blr[nt][1]);
                    mma_bf16(acc[mt][nt], al[mt][0], al[mt][1], al[mt][2], al[mt][3],
                             bh[nt][0], bh[nt][1]);
                }
        }
        __syncthreads();
    }

#pragma unroll
    for (int mt = 0; mt < 4; mt++) {
#pragma unroll
        for (int nt = 0; nt < 4; nt++) {
            int row = mtile + mloc + mt * 16 + lq;
            int col = nloc + nt * 8 + lr * 2;
            float bx = bias[col], by = bias[col + 1];
            *(float2*)&out[(size_t)row * HIDN + col] =
                make_float2(acc[mt][nt][0] + bx, acc[mt][nt][1] + by);
            *(float2*)&out[(size_t)(row + 8) * HIDN + col] =
                make_float2(acc[mt][nt][2] + bx, acc[mt][nt][3] + by);
        }
    }
}

// ---------------- fused score + online-softmax + aggregation + BN stats -----
// warp per node (degree-sorted); records staged in smem (8-edge segments,
// double-buffered, coalesced 16-lane loads); 4-edge batched compute.
__global__ void k_fused(const float* __restrict__ We_l, const float* __restrict__ att_l,
                        const float* __restrict__ bconv_l, int l) {
    __shared__ float4 s_rec[8][2][16];
    __shared__ float s_sum[8][HIDN];
    __shared__ float s_sq[8][HIDN];
    int lane = threadIdx.x & 31;
    int wid = threadIdx.x >> 5;
    int node = g_nodeorder[blockIdx.x * 8 + wid];
    int ch = ((lane >> 3) << 5) + ((lane & 7) << 2);   // head*32 + sub*4

    float4 w0 = *(const float4*)(We_l + 0 * HIDN + ch);
    float4 w1 = *(const float4*)(We_l + 1 * HIDN + ch);
    float4 w2 = *(const float4*)(We_l + 2 * HIDN + ch);
    float4 w3 = *(const float4*)(We_l + 3 * HIDN + ch);
    float4 w4 = *(const float4*)(We_l + 4 * HIDN + ch);
    float4 w5 = *(const float4*)(We_l + 5 * HIDN + ch);
    float4 at = *(const float4*)(att_l + ch);
    float4 xr4 = *(const float4*)(g_xr + (size_t)node * HIDN + ch);
    float4 bc = *(const float4*)(bconv_l + ch);

    int beg = g_rowoff[node], end = g_rowoff[node + 1];
    int nseg = (end - beg) >> 3;

    float m = -1e30f, den = 0.f;
    float ax = 0.f, ay = 0.f, az = 0.f, aw = 0.f;

    const float4* rec = (const float4*)g_erec;

    auto edge_score = [&](const float4& A, const float4& B, const float4& X) -> float {
        float ee_x = A.y*w0.x + A.z*w1.x + A.w*w2.x + B.x*w3.x + B.y*w4.x + B.z*w5.x;
        float ee_y = A.y*w0.y + A.z*w1.y + A.w*w2.y + B.x*w3.y + B.y*w4.y + B.z*w5.y;
        float ee_z = A.y*w0.z + A.z*w1.z + A.w*w2.z + B.x*w3.z + B.y*w4.z + B.z*w5.z;
        float ee_w = A.y*w0.w + A.z*w1.w + A.w*w2.w + B.x*w3.w + B.y*w4.w + B.z*w5.w;
        float t0 = X.x + xr4.x + ee_x; t0 = (t0 > 0.f) ? t0 : 0.2f * t0;
        float t1 = X.y + xr4.y + ee_y; t1 = (t1 > 0.f) ? t1 : 0.2f * t1;
        float t2 = X.z + xr4.z + ee_z; t2 = (t2 > 0.f) ? t2 : 0.2f * t2;
        float t3 = X.w + xr4.w + ee_w; t3 = (t3 > 0.f) ? t3 : 0.2f * t3;
        return t0 * at.x + t1 * at.y + t2 * at.z + t3 * at.w;
    };

    // prefetch segment 0 (coalesced: 16 lanes load 16 consecutive float4s)
    if (nseg > 0 && lane < 16)
        s_rec[wid][0][lane] = rec[2 * (size_t)beg + lane];
    __syncwarp();

    for (int s = 0; s < nseg; s++) {
        int buf = s & 1;
        if (s + 1 < nseg && lane < 16)
            s_rec[wid][buf ^ 1][lane] = rec[2 * (size_t)(beg + 8 * (s + 1)) + lane];

#pragma unroll
        for (int gq = 0; gq < 2; gq++) {
            const float4* rp = &s_rec[wid][buf][gq * 8];
            float4 X[4];
#pragma unroll
            for (int u = 0; u < 4; u++)
                X[u] = *(const float4*)(g_xl +
                        (size_t)__float_as_int(rp[2 * u].x) * HIDN + ch);

            float sp0 = edge_score(rp[0], rp[1], X[0]);
            float sp1 = edge_score(rp[2], rp[3], X[1]);
            float sp2 = edge_score(rp[4], rp[5], X[2]);
            float sp3 = edge_score(rp[6], rp[7], X[3]);
#pragma unroll
            for (int off = 1; off <= 4; off <<= 1) {
                sp0 += __shfl_xor_sync(0xffffffffu, sp0, off);
                sp1 += __shfl_xor_sync(0xffffffffu, sp1, off);
                sp2 += __shfl_xor_sync(0xffffffffu, sp2, off);
                sp3 += __shfl_xor_sync(0xffffffffu, sp3, off);
            }

            float gm = fmaxf(fmaxf(sp0, sp1), fmaxf(sp2, sp3));
            float mn = fmaxf(m, gm);
            float r  = __expf(m - mn);
            float e0 = __expf(sp0 - mn);
            float e1 = __expf(sp1 - mn);
            float e2 = __expf(sp2 - mn);
            float e3 = __expf(sp3 - mn);
            ax = ax * r + e0 * X[0].x + e1 * X[1].x + e2 * X[2].x + e3 * X[3].x;
            ay = ay * r + e0 * X[0].y + e1 * X[1].y + e2 * X[2].y + e3 * X[3].y;
            az = az * r + e0 * X[0].z + e1 * X[1].z + e2 * X[2].z + e3 * X[3].z;
            aw = aw * r + e0 * X[0].w + e1 * X[1].w + e2 * X[2].w + e3 * X[3].w;
            den = den * r + e0 + e1 + e2 + e3;
            m = mn;
        }
        __syncwarp();
    }

    // tail (<8 edges): direct gmem loads
    for (int j = beg + nseg * 8; j < end; j++) {
        float4 A = rec[2 * (size_t)j];
        float4 B = rec[2 * (size_t)j + 1];
        float4 X = *(const float4*)(g_xl + (size_t)__float_as_int(A.x) * HIDN + ch);
        float sp = edge_score(A, B, X);
#pragma unroll
        for (int off = 1; off <= 4; off <<= 1)
            sp += __shfl_xor_sync(0xffffffffu, sp, off);
        float mn = fmaxf(m, sp);
        float r  = __expf(m - mn);
        float wg = __expf(sp - mn);
        ax = ax * r + wg * X.x;
        ay = ay * r + wg * X.y;
        az = az * r + wg * X.z;
        aw = aw * r + wg * X.w;
        den = den * r + wg;
        m = mn;
    }

    float inv = 1.0f / den;
    float4 o;
    o.x = ax * inv + bc.x;
    o.y = ay * inv + bc.y;
    o.z = az * inv + bc.z;
    o.w = aw * inv + bc.w;
    *(float4*)(g_conv + (size_t)node * HIDN + ch) = o;

    *(float4*)&s_sum[wid][ch] = o;
    *(float4*)&s_sq[wid][ch] = make_float4(o.x * o.x, o.y * o.y, o.z * o.z, o.w * o.w);
    __syncthreads();
    int t = threadIdx.x;
    if (t < HIDN) {
        float s = 0.f, q = 0.f;
#pragma unroll
        for (int w = 0; w < 8; w++) { s += s_sum[w][t]; q += s_sq[w][t]; }
        atomicAdd(&g_stats[l * 2 * HIDN + t], s);
        atomicAdd(&g_stats[l * 2 * HIDN + HIDN + t], q);
    }
}

// ---------------- final BN apply (layer 7) + residual + relu ----------------
__global__ void k_bnfinal(const float* __restrict__ gamma_l, const float* __restrict__ beta_l,
                          const float* __restrict__ res, float* __restrict__ out, int l) {
    int j4 = blockIdx.x * blockDim.x + threadIdx.x;
    if (j4 >= NN * HIDN / 4) return;
    int f4 = (j4 & 31);
    const float invN = 1.0f / (float)NN;

    float4 sum4 = ((const float4*)(g_stats + l * 2 * HIDN))[f4];
    float4 sq4  = ((const float4*)(g_stats + l * 2 * HIDN + HIDN))[f4];
    float4 gm = ((const float4*)gamma_l)[f4];
    float4 bt = ((const float4*)beta_l)[f4];
    float4 c = ((const float4*)g_conv)[j4];
    float4 r4 = ((const float4*)res)[j4];

    float4 y;
    float mean = sum4.x * invN, var = sq4.x * invN - mean * mean;
    y.x = gm.x * (c.x - mean) * rsqrtf(var + 1e-5f) + bt.x + r4.x;
    mean = sum4.y * invN; var = sq4.y * invN - mean * mean;
    y.y = gm.y * (c.y - mean) * rsqrtf(var + 1e-5f) + bt.y + r4.y;
    mean = sum4.z * invN; var = sq4.z * invN - mean * mean;
    y.z = gm.z * (c.z - mean) * rsqrtf(var + 1e-5f) + bt.z + r4.z;
    mean = sum4.w * invN; var = sq4.w * invN - mean * mean;
    y.w = gm.w * (c.w - mean) * rsqrtf(var + 1e-5f) + bt.w + r4.w;

    y.x = fmaxf(y.x, 0.f); y.y = fmaxf(y.y, 0.f);
    y.z = fmaxf(y.z, 0.f); y.w = fmaxf(y.w, 0.f);
    ((float4*)out)[j4] = y;
}

// ---------------- mean pooling per graph (run-accumulated, batch sorted) ----
__global__ void k_pool(const int* __restrict__ batch, const float* __restrict__ h) {
    int t = threadIdx.x;
    int f4 = t & 31;
    int grp = t >> 5;
    int n0 = (blockIdx.x * 8 + grp) * 8;
    float4 acc = make_float4(0.f, 0.f, 0.f, 0.f);
    float cnt = 0.f;
    int curb = __ldg(&batch[n0]);
#pragma unroll
    for (int k = 0; k < 8; k++) {
        int n = n0 + k;
        int b = __ldg(&batch[n]);
        if (b != curb) {
            atomicAdd(&g_pooled[curb * HIDN + f4 * 4 + 0], acc.x);
            atomicAdd(&g_pooled[curb * HIDN + f4 * 4 + 1], acc.y);
            atomicAdd(&g_pooled[curb * HIDN + f4 * 4 + 2], acc.z);
            atomicAdd(&g_pooled[curb * HIDN + f4 * 4 + 3], acc.w);
            if (f4 == 0) atomicAdd(&g_gcnt[curb], cnt);
            acc = make_float4(0.f, 0.f, 0.f, 0.f);
            cnt = 0.f;
            curb = b;
        }
        float4 v = ((const float4*)h)[n * 32 + f4];
        acc.x += v.x; acc.y += v.y; acc.z += v.z; acc.w += v.w;
        cnt += 1.f;
    }
    atomicAdd(&g_pooled[curb * HIDN + f4 * 4 + 0], acc.x);
    atomicAdd(&g_pooled[curb * HIDN + f4 * 4 + 1], acc.y);
    atomicAdd(&g_pooled[curb * HIDN + f4 * 4 + 2], acc.z);
    atomicAdd(&g_pooled[curb * HIDN + f4 * 4 + 3], acc.w);
    if (f4 == 0) atomicAdd(&g_gcnt[curb], cnt);
}

// ---------------- final MLP: relu(pooled@W1+b1)@W2+b2 ----------------------
__global__ void k_mlp(const float* __restrict__ W1, const float* __restrict__ b1,
                      const float* __restrict__ W2, const float* __restrict__ b2,
                      float* __restrict__ out) {
    __shared__ float pl[HIDN];
    __shared__ float hid[64];
    int g = blockIdx.x;
    int t = threadIdx.x;
    float inv = 1.0f / fmaxf(g_gcnt[g], 1.0f);
    for (int j = t; j < HIDN; j += 64) pl[j] = g_pooled[g * HIDN + j] * inv;
    __syncthreads();
    float a = b1[t];
    for (int k = 0; k < HIDN; k++) a += pl[k] * W1[k * 64 + t];
    hid[t] = fmaxf(a, 0.f);
    __syncthreads();
    if (t < 3) {
        float lg = b2[t];
        for (int k = 0; k < 64; k++) lg += hid[k] * W2[k * 3 + t];
        out[g * 3 + t] = lg;
    }
}

// ---------------- launch ----------------------------------------------------
extern "C" void kernel_launch(void* const* d_in, const int* in_sizes, int n_in,
                              void* d_out, int out_size) {
    const float* x     = (const float*)d_in[0];
    const int*   ei    = (const int*)d_in[1];
    const float* ea    = (const float*)d_in[2];
    const int*   batch = (const int*)d_in[3];
    const float* Win   = (const float*)d_in[4];
    const float* b_in  = (const float*)d_in[5];
    const float* Wl    = (const float*)d_in[6];
    const float* bl    = (const float*)d_in[7];
    const float* Wr    = (const float*)d_in[8];
    const float* br    = (const float*)d_in[9];
    const float* We    = (const float*)d_in[10];
    const float* att   = (const float*)d_in[11];
    const float* bconv = (const float*)d_in[12];
    const float* gamma = (const float*)d_in[13];
    const float* beta  = (const float*)d_in[14];
    const float* W1    = (const float*)d_in[15];
    const float* b1    = (const float*)d_in[16];
    const float* W2    = (const float*)d_in[17];
    const float* b2    = (const float*)d_in[18];
    float* out = (float*)d_out;

    float *bufA = nullptr, *bufB = nullptr, *convp = nullptr, *statsp = nullptr;
    cudaGetSymbolAddress((void**)&bufA, g_bufA);
    cudaGetSymbolAddress((void**)&bufB, g_bufB);
    cudaGetSymbolAddress((void**)&convp, g_conv);
    cudaGetSymbolAddress((void**)&statsp, g_stats);
    __nv_bfloat16* whi = nullptr;
    __nv_bfloat16* wlo = nullptr;
    cudaGetSymbolAddress((void**)&whi, g_w_hi);
    cudaGetSymbolAddress((void**)&wlo, g_w_lo);

    k_init<<<64, 256>>>();
    k_wsplit<<<(NLAY * 2 * HIDN * HIDN + 255) / 256, 256>>>(Wl, Wr);
    k_deg<<<(EE + 255) / 256, 256>>>(ei);
    k_scanA<<<64, 256>>>();
    k_scanB<<<1, 192>>>();
    k_scanC<<<64, 256>>>();
    k_scatter<<<(EF + 255) / 256, 256>>>(ei, ea);
    k_loopattr<<<NN / 8, 256>>>();
    k_ingemm<<<NN, HIDN>>>(x, Win, b_in);

    dim3 ggrid(NN / 128, 2);
    for (int l = 0; l < NLAY; l++) {
        const float* conv_src = (l == 0) ? bufA : convp;
        const float* st = (l == 0) ? nullptr : statsp + (size_t)(l - 1) * 2 * HIDN;
        const float* gm = (l == 0) ? nullptr : gamma + (size_t)(l - 1) * HIDN;
        const float* bt = (l == 0) ? nullptr : beta + (size_t)(l - 1) * HIDN;
        const float* res = nullptr;
        float* hout = nullptr;
        if (l == 2) { res = bufA; hout = bufB; }
        if (l == 4) { res = bufB; hout = bufA; }
        if (l == 6) { res = bufA; hout = bufB; }

        k_gemm_bf16<<<ggrid, 256>>>(whi + (size_t)l * 2 * HIDN * HIDN,
                                    wlo + (size_t)l * 2 * HIDN * HIDN,
                                    bl + (size_t)l * HIDN, br + (size_t)l * HIDN,
                                    conv_src, st, gm, bt, res, hout);
        k_fused<<<NN / 8, 256>>>(We + (size_t)l * EDIM * HIDN,
                                 att + (size_t)l * NHEAD * HC,
                                 bconv + (size_t)l * HIDN, l);
    }

    k_bnfinal<<<NN * HIDN / 4 / 256, 256>>>(gamma + 7 * HIDN, beta + 7 * HIDN,
                                            bufB, bufA, 7);
    k_pool<<<NN / 64, 256>>>(batch, bufA);
    k_mlp<<<GG, 64>>>(W1, b1, W2, b2, out);
}

// round 16
// speedup vs baseline: 1.1302x; 1.1302x over previous
#include <cuda_runtime.h>
#include <cuda_bf16.h>
#include <cstdint>

#define NN 16384
#define EE 393216
#define EF (EE + NN)      // 409600 edges incl. self loops
#define GG 256
#define HIDN 128
#define NHEAD 4
#define HC 32
#define NLAY 8
#define NDIM 21
#define EDIM 6

// ---------------- scratch (device globals; no allocation allowed) ----------
__device__ float g_bufA[NN * HIDN];
__device__ float g_bufB[NN * HIDN];
__device__ float g_xl[NN * HIDN];
__device__ float g_xr[NN * HIDN];
__device__ float g_conv[NN * HIDN];
__device__ int   g_deg[NN];
__device__ int   g_rowoff[NN + 1];
__device__ int   g_rank[EE];
__device__ int   g_bsum[64];
__device__ int   g_boff[64];
__device__ int   g_dhist[128];
__device__ int   g_dbase[128];
__device__ int   g_rank2[NN];
__device__ int   g_nodeorder[NN];
__device__ float g_erec[(size_t)EF * 8];   // [src_bits, ea0..ea5, pad] per edge
__device__ float g_stats[NLAY * 2 * HIDN];
__device__ float g_pooled[GG * HIDN];
__device__ float g_gcnt[GG];
__device__ __nv_bfloat16 g_w_hi[NLAY * 2 * HIDN * HIDN];
__device__ __nv_bfloat16 g_w_lo[NLAY * 2 * HIDN * HIDN];

// ---------------- helpers ------------------------------------------------------
__device__ __forceinline__ void bf_split(float f, __nv_bfloat16& hi, __nv_bfloat16& lo) {
    hi = __float2bfloat16(f);
    lo = __float2bfloat16(f - __bfloat162float(hi));
}
__device__ __forceinline__ uint32_t bf_pack(__nv_bfloat16 a, __nv_bfloat16 b) {
    __nv_bfloat162 p(a, b);
    return *(uint32_t*)&p;
}
__device__ __forceinline__ void mma_bf16(float* d, uint32_t a0, uint32_t a1,
                                         uint32_t a2, uint32_t a3,
                                         uint32_t b0, uint32_t b1) {
    asm volatile(
        "mma.sync.aligned.m16n8k16.row.col.f32.bf16.bf16.f32 "
        "{%0,%1,%2,%3}, {%4,%5,%6,%7}, {%8,%9}, {%0,%1,%2,%3};"
        : "+f"(d[0]), "+f"(d[1]), "+f"(d[2]), "+f"(d[3])
        : "r"(a0), "r"(a1), "r"(a2), "r"(a3), "r"(b0), "r"(b1));
}

// ---------------- init ------------------------------------------------------
__global__ void k_init() {
    int i = blockIdx.x * blockDim.x + threadIdx.x;
    int stride = gridDim.x * blockDim.x;
    for (int j = i; j < NN; j += stride) g_deg[j] = 0;
    for (int j = i; j < 128; j += stride) g_dhist[j] = 0;
    for (int j = i; j < NLAY * 2 * HIDN; j += stride) g_stats[j] = 0.f;
    for (int j = i; j < GG * HIDN; j += stride) g_pooled[j] = 0.f;
    for (int j = i; j < GG; j += stride) g_gcnt[j] = 0.f;
}

// ---------------- weight split + transpose (once per launch) ----------------
__global__ void k_wsplit(const float* __restrict__ Wl, const float* __restrict__ Wr) {
    int idx = blockIdx.x * blockDim.x + threadIdx.x;
    if (idx >= NLAY * 2 * HIDN * HIDN) return;
    int l2 = idx >> 14;
    int rem = idx & 16383;
    int n = rem >> 7;
    int k = rem & 127;
    int l = l2 >> 1, side = l2 & 1;
    const float* W = (side ? Wr : Wl) + (size_t)l * HIDN * HIDN;
    float v = W[k * HIDN + n];
    __nv_bfloat16 hi, lo;
    bf_split(v, hi, lo);
    g_w_hi[idx] = hi;
    g_w_lo[idx] = lo;
}

// ---------------- degree count + within-dst rank -----------------------------
__global__ void k_deg(const int* __restrict__ ei) {
    int e = blockIdx.x * blockDim.x + threadIdx.x;
    if (e >= EE) return;
    g_rank[e] = atomicAdd(&g_deg[ei[EE + e]], 1);
}

// ---------------- scanA: rowoff block-scan + degree histogram (fused) -------
__global__ void k_scanA() {      // 64 blocks x 256 threads, 1 node each
    __shared__ int wsums[8];
    int n = blockIdx.x * 256 + threadIdx.x;
    int lane = threadIdx.x & 31, w = threadIdx.x >> 5;
    int d = g_deg[n];
    g_rank2[n] = atomicAdd(&g_dhist[min(d, 127)], 1);
    int v = d + 1;
    int x = v;
#pragma unroll
    for (int off = 1; off < 32; off <<= 1) {
        int u = __shfl_up_sync(0xffffffffu, x, off);
        if (lane >= off) x += u;
    }
    if (lane == 31) wsums[w] = x;
    __syncthreads();
    if (w == 0) {
        int s = (lane < 8) ? wsums[lane] : 0;
#pragma unroll
        for (int off = 1; off < 8; off <<= 1) {
            int u = __shfl_up_sync(0xffffffffu, s, off);
            if (lane >= off) s += u;
        }
        if (lane < 8) wsums[lane] = s;
    }
    __syncthreads();
    int excl = x - v + (w ? wsums[w - 1] : 0);
    g_rowoff[n] = excl;
    if (threadIdx.x == 255) g_bsum[blockIdx.x] = excl + v;
}

// ---------------- scanB: block-sum scan (64) + dhist scan (128), one block --
__global__ void k_scanB() {      // 1 block, 192 threads
    __shared__ int ws[2];
    __shared__ int ws2[4];
    int t = threadIdx.x;
    int v = 0, x = 0;
    if (t < 64) {
        int lane = t & 31, w = t >> 5;
        v = g_bsum[t];
        x = v;
#pragma unroll
        for (int off = 1; off < 32; off <<= 1) {
            int u = __shfl_up_sync(0xffffffffu, x, off);
            if (lane >= off) x += u;
        }
        if (lane == 31) ws[w] = x;
    } else {
        int t2 = t - 64;
        int lane = t2 & 31, w2 = t2 >> 5;
        v = g_dhist[t2];
        x = v;
#pragma unroll
        for (int off = 1; off < 32; off <<= 1) {
            int u = __shfl_up_sync(0xffffffffu, x, off);
            if (lane >= off) x += u;
        }
        if (lane == 31) ws2[w2] = x;
    }
    __syncthreads();
    if (t < 64) {
        int w = t >> 5;
        int excl = x - v + (w ? ws[0] : 0);
        g_boff[t] = excl;
        if (t == 63) g_rowoff[NN] = excl + v;
    } else {
        int t2 = t - 64;
        int w2 = t2 >> 5;
        int base = 0;
#pragma unroll
        for (int i = 0; i < 4; i++) if (i < w2) base += ws2[i];
        g_dbase[t2] = x - v + base;
    }
}

// ---------------- scanC: rowoff fixup + degree-sorted placement (fused) -----
__global__ void k_scanC() {      // 64 blocks x 256
    int n = blockIdx.x * 256 + threadIdx.x;
    g_rowoff[n] += g_boff[blockIdx.x];
    int b = min(g_deg[n], 127);
    g_nodeorder[g_dbase[b] + g_rank2[n]] = n;
}

// ---------------- scatter: self-loop at slot 0, real edges after (no atomic) -
__global__ void k_scatter(const int* __restrict__ ei, const float* __restrict__ ea) {
    int t = blockIdx.x * blockDim.x + threadIdx.x;
    if (t >= EF) return;
    if (t < EE) {
        int s = ei[t], d = ei[EE + t];
        int pos = g_rowoff[d] + 1 + g_rank[t];
        const float2* src = (const float2*)(ea + (size_t)t * EDIM);  // 8B-aligned
        float2 p0 = __ldg(&src[0]), p1 = __ldg(&src[1]), p2 = __ldg(&src[2]);
        float4* dst = (float4*)(g_erec + (size_t)pos * 8);
        dst[0] = make_float4(__int_as_float(s), p0.x, p0.y, p1.x);
        dst[1] = make_float4(p1.y, p2.x, p2.y, 0.f);
    } else {
        int n = t - EE;
        g_erec[(size_t)g_rowoff[n] * 8] = __int_as_float(n);   // self loop src
    }
}

// ---------------- self-loop attr = mean of incoming (warp per node) ---------
__global__ void k_loopattr() {
    int lane = threadIdx.x & 31;
    int n = blockIdx.x * 8 + (threadIdx.x >> 5);
    if (n >= NN) return;
    int beg = g_rowoff[n], end = g_rowoff[n + 1];
    float s0 = 0.f, s1 = 0.f, s2 = 0.f, s3 = 0.f, s4 = 0.f, s5 = 0.f;
    const float4* rec = (const float4*)g_erec;
    for (int j = beg + 1 + lane; j < end; j += 32) {
        float4 A = rec[2 * (size_t)j];
        float4 B = rec[2 * (size_t)j + 1];
        s0 += A.y; s1 += A.z; s2 += A.w;
        s3 += B.x; s4 += B.y; s5 += B.z;
    }
#pragma unroll
    for (int off = 16; off > 0; off >>= 1) {
        s0 += __shfl_xor_sync(0xffffffffu, s0, off);
        s1 += __shfl_xor_sync(0xffffffffu, s1, off);
        s2 += __shfl_xor_sync(0xffffffffu, s2, off);
        s3 += __shfl_xor_sync(0xffffffffu, s3, off);
        s4 += __shfl_xor_sync(0xffffffffu, s4, off);
        s5 += __shfl_xor_sync(0xffffffffu, s5, off);
    }
    if (lane == 0) {
        float inv = 1.0f / fmaxf((float)(end - beg - 1), 1.0f);
        float4* dst = (float4*)(g_erec + (size_t)beg * 8);
        float src = g_erec[(size_t)beg * 8];
        dst[0] = make_float4(src, s0 * inv, s1 * inv, s2 * inv);
        dst[1] = make_float4(s3 * inv, s4 * inv, s5 * inv, 0.f);
    }
}

// ---------------- input projection: h = relu(x @ Win + b_in) ---------------
__global__ void k_ingemm(const float* __restrict__ x, const float* __restrict__ Win,
                         const float* __restrict__ b_in) {
    __shared__ float xs[NDIM];
    int n = blockIdx.x;
    int f = threadIdx.x;
    if (f < NDIM) xs[f] = x[n * NDIM + f];
    __syncthreads();
    float a = b_in[f];
#pragma unroll
    for (int k = 0; k < NDIM; k++) a += xs[k] * Win[k * HIDN + f];
    g_bufA[n * HIDN + f] = fmaxf(a, 0.f);
}

// ---------------- tensor-core dual GEMM with fused BN-apply in A-staging ----
#define GPAD 20
__global__ void __launch_bounds__(256)
k_gemm_bf16(const __nv_bfloat16* __restrict__ whi, const __nv_bfloat16* __restrict__ wlo,
            const float* __restrict__ bl, const float* __restrict__ br,
            const float* __restrict__ conv_src,
            const float* __restrict__ stats,
            const float* __restrict__ gamma_l, const float* __restrict__ beta_l,
            const float* __restrict__ res, float* __restrict__ hout) {
    __shared__ uint32_t sAh[128 * GPAD];
    __shared__ uint32_t sAl[128 * GPAD];
    __shared__ uint32_t sBh[128 * GPAD];
    __shared__ uint32_t sBl[128 * GPAD];
    __shared__ float sa[HIDN], sb[HIDN];

    const float* bias = blockIdx.y ? br : bl;
    float* out        = blockIdx.y ? g_xr : g_xl;
    const uint32_t* Wh  = (const uint32_t*)(whi + (size_t)blockIdx.y * HIDN * HIDN);
    const uint32_t* Wl_ = (const uint32_t*)(wlo + (size_t)blockIdx.y * HIDN * HIDN);

    int t = threadIdx.x;
    if (t < HIDN) {
        float A = 1.f, Bc = 0.f;
        if (gamma_l) {
            const float invN = 1.0f / (float)NN;
            float mean = stats[t] * invN;
            float var = stats[HIDN + t] * invN - mean * mean;
            float istd = rsqrtf(var + 1e-5f);
            A = gamma_l[t] * istd;
            Bc = beta_l[t] - A * mean;
        }
        sa[t] = A; sb[t] = Bc;
    }
    __syncthreads();

    int lane = t & 31;
    int warp = t >> 5;
    int mloc = (warp & 1) * 64;
    int nloc = (warp >> 1) * 32;
    int mtile = blockIdx.x * 128;
    int lq = lane >> 2;
    int lr = lane & 3;
    bool wout = (hout != nullptr) && (blockIdx.y == 0);

    float acc[4][4][4];
#pragma unroll
    for (int mt = 0; mt < 4; mt++)
#pragma unroll
        for (int nt = 0; nt < 4; nt++)
#pragma unroll
            for (int i = 0; i < 4; i++) acc[mt][nt][i] = 0.f;

#pragma unroll
    for (int kc = 0; kc < 4; kc++) {
        int kb = kc * 32;
        int kbase = kc * 16;
#pragma unroll
        for (int it = 0; it < 4; it++) {
            int i4 = it * 256 + t;
            int row = i4 >> 3;
            int c8 = i4 & 7;
            int gcol = kb + c8 * 4;
            size_t gidx = (size_t)(mtile + row) * HIDN + gcol;
            float4 c = *(const float4*)(conv_src + gidx);
            float4 y;
            y.x = sa[gcol] * c.x + sb[gcol];
            y.y = sa[gcol + 1] * c.y + sb[gcol + 1];
            y.z = sa[gcol + 2] * c.z + sb[gcol + 2];
            y.w = sa[gcol + 3] * c.w + sb[gcol + 3];
            if (res) {
                float4 r4 = *(const float4*)(res + gidx);
                y.x += r4.x; y.y += r4.y; y.z += r4.z; y.w += r4.w;
            }
            y.x = fmaxf(y.x, 0.f); y.y = fmaxf(y.y, 0.f);
            y.z = fmaxf(y.z, 0.f); y.w = fmaxf(y.w, 0.f);
            if (wout) *(float4*)(hout + gidx) = y;
            __nv_bfloat16 h0, l0, h1, l1, h2, l2, h3, l3;
            bf_split(y.x, h0, l0); bf_split(y.y, h1, l1);
            bf_split(y.z, h2, l2); bf_split(y.w, h3, l3);
            sAh[row * GPAD + c8 * 2]     = bf_pack(h0, h1);
            sAh[row * GPAD + c8 * 2 + 1] = bf_pack(h2, h3);
            sAl[row * GPAD + c8 * 2]     = bf_pack(l0, l1);
            sAl[row * GPAD + c8 * 2 + 1] = bf_pack(l2, l3);
        }
#pragma unroll
        for (int it = 0; it < 2; it++) {
            int i4 = it * 256 + t;
            int row = i4 >> 2, u = (i4 & 3) << 2;
            *(uint4*)(sBh + row * GPAD + u) =
                *(const uint4*)(Wh + (size_t)row * 64 + kbase + u);
            *(uint4*)(sBl + row * GPAD + u) =
                *(const uint4*)(Wl_ + (size_t)row * 64 + kbase + u);
        }
        __syncthreads();

#pragma unroll
        for (int ks = 0; ks < 2; ks++) {
            int c0 = ks * 8 + lr;
            uint32_t ah[4][4], al[4][4];
#pragma unroll
            for (int mt = 0; mt < 4; mt++) {
                int r0 = (mloc + mt * 16 + lq) * GPAD;
                int r1 = r0 + 8 * GPAD;
                ah[mt][0] = sAh[r0 + c0];
                ah[mt][1] = sAh[r1 + c0];
                ah[mt][2] = sAh[r0 + c0 + 4];
                ah[mt][3] = sAh[r1 + c0 + 4];
                al[mt][0] = sAl[r0 + c0];
                al[mt][1] = sAl[r1 + c0];
                al[mt][2] = sAl[r0 + c0 + 4];
                al[mt][3] = sAl[r1 + c0 + 4];
            }
            uint32_t bh[4][2], blr[4][2];
#pragma unroll
            for (int nt = 0; nt < 4; nt++) {
                int rb = (nloc + nt * 8 + lq) * GPAD;
                bh[nt][0]  = sBh[rb + c0];
                bh[nt][1]  = sBh[rb + c0 + 4];
                blr[nt][0] = sBl[rb + c0];
                blr[nt][1] = sBl[rb + c0 + 4];
            }
#pragma unroll
            for (int mt = 0; mt < 4; mt++)
#pragma unroll
                for (int nt = 0; nt < 4; nt++) {
                    mma_bf16(acc[mt][nt], ah[mt][0], ah[mt][1], ah[mt][2], ah[mt][3],
                             bh[nt][0], bh[nt][1]);
                    mma_bf16(acc[mt][nt], ah[mt][0], ah[mt][1], ah[mt][2], ah[mt][3],
                             blr[nt][0], blr[nt][1]);
                    mma_bf16(acc[mt][nt], al[mt][0], al[mt][1], al[mt][2], al[mt][3],
                             bh[nt][0], bh[nt][1]);
                }
        }
        __syncthreads();
    }

#pragma unroll
    for (int mt = 0; mt < 4; mt++) {
#pragma unroll
        for (int nt = 0; nt < 4; nt++) {
            int row = mtile + mloc + mt * 16 + lq;
            int col = nloc + nt * 8 + lr * 2;
            float bx = bias[col], by = bias[col + 1];
            *(float2*)&out[(size_t)row * HIDN + col] =
                make_float2(acc[mt][nt][0] + bx, acc[mt][nt][1] + by);
            *(float2*)&out[(size_t)(row + 8) * HIDN + col] =
                make_float2(acc[mt][nt][2] + bx, acc[mt][nt][3] + by);
        }
    }
}

// ---------------- fused score + online-softmax + aggregation + BN stats -----
// warp per node (degree-sorted order); lane = head*8 + sub; 4-edge batched.
// __launch_bounds__(256, 2): cap regs at 128 to get 2 blocks/SM resident.
__global__ void __launch_bounds__(256, 2)
k_fused(const float* __restrict__ We_l, const float* __restrict__ att_l,
        const float* __restrict__ bconv_l, int l) {
    __shared__ float s_sum[8][HIDN];
    __shared__ float s_sq[8][HIDN];
    int lane = threadIdx.x & 31;
    int wid = threadIdx.x >> 5;
    int node = g_nodeorder[blockIdx.x * 8 + wid];
    int ch = ((lane >> 3) << 5) + ((lane & 7) << 2);   // head*32 + sub*4

    float4 w0 = *(const float4*)(We_l + 0 * HIDN + ch);
    float4 w1 = *(const float4*)(We_l + 1 * HIDN + ch);
    float4 w2 = *(const float4*)(We_l + 2 * HIDN + ch);
    float4 w3 = *(const float4*)(We_l + 3 * HIDN + ch);
    float4 w4 = *(const float4*)(We_l + 4 * HIDN + ch);
    float4 w5 = *(const float4*)(We_l + 5 * HIDN + ch);
    float4 at = *(const float4*)(att_l + ch);
    float4 xr4 = *(const float4*)(g_xr + (size_t)node * HIDN + ch);

    int beg = g_rowoff[node], end = g_rowoff[node + 1];

    float m = -1e30f, den = 0.f;
    float ax = 0.f, ay = 0.f, az = 0.f, aw = 0.f;

    const float4* rec = (const float4*)g_erec;

    auto edge_score = [&](const float4& A, const float4& B, const float4& X) -> float {
        float ee_x = A.y*w0.x + A.z*w1.x + A.w*w2.x + B.x*w3.x + B.y*w4.x + B.z*w5.x;
        float ee_y = A.y*w0.y + A.z*w1.y + A.w*w2.y + B.x*w3.y + B.y*w4.y + B.z*w5.y;
        float ee_z = A.y*w0.z + A.z*w1.z + A.w*w2.z + B.x*w3.z + B.y*w4.z + B.z*w5.z;
        float ee_w = A.y*w0.w + A.z*w1.w + A.w*w2.w + B.x*w3.w + B.y*w4.w + B.z*w5.w;
        float t0 = X.x + xr4.x + ee_x; t0 = (t0 > 0.f) ? t0 : 0.2f * t0;
        float t1 = X.y + xr4.y + ee_y; t1 = (t1 > 0.f) ? t1 : 0.2f * t1;
        float t2 = X.z + xr4.z + ee_z; t2 = (t2 > 0.f) ? t2 : 0.2f * t2;
        float t3 = X.w + xr4.w + ee_w; t3 = (t3 > 0.f) ? t3 : 0.2f * t3;
        return t0 * at.x + t1 * at.y + t2 * at.z + t3 * at.w;
    };

    int j = beg;
    int nfull = (end - beg) & ~3;
    int gend = beg + nfull;

    if (j < gend) {
        float4 A[4], Bv[4];
#pragma unroll
        for (int u = 0; u < 4; u++) {
            A[u]  = rec[2 * (size_t)(j + u)];
            Bv[u] = rec[2 * (size_t)(j + u) + 1];
        }
        for (; j < gend; j += 4) {
            float4 X[4];
#pragma unroll
            for (int u = 0; u < 4; u++)
                X[u] = *(const float4*)(g_xl + (size_t)__float_as_int(A[u].x) * HIDN + ch);

            float4 An[4], Bn[4];
            if (j + 8 <= gend) {
#pragma unroll
                for (int u = 0; u < 4; u++) {
                    An[u] = rec[2 * (size_t)(j + 4 + u)];
                    Bn[u] = rec[2 * (size_t)(j + 4 + u) + 1];
                }
            }

            float sp0 = edge_score(A[0], Bv[0], X[0]);
            float sp1 = edge_score(A[1], Bv[1], X[1]);
            float sp2 = edge_score(A[2], Bv[2], X[2]);
            float sp3 = edge_score(A[3], Bv[3], X[3]);
#pragma unroll
            for (int off = 1; off <= 4; off <<= 1) {
                sp0 += __shfl_xor_sync(0xffffffffu, sp0, off);
                sp1 += __shfl_xor_sync(0xffffffffu, sp1, off);
                sp2 += __shfl_xor_sync(0xffffffffu, sp2, off);
                sp3 += __shfl_xor_sync(0xffffffffu, sp3, off);
            }

            float gm = fmaxf(fmaxf(sp0, sp1), fmaxf(sp2, sp3));
            float mn = fmaxf(m, gm);
            float r  = __expf(m - mn);
            float e0 = __expf(sp0 - mn);
            float e1 = __expf(sp1 - mn);
            float e2 = __expf(sp2 - mn);
            float e3 = __expf(sp3 - mn);
            ax = ax * r + e0 * X[0].x + e1 * X[1].x + e2 * X[2].x + e3 * X[3].x;
            ay = ay * r + e0 * X[0].y + e1 * X[1].y + e2 * X[2].y + e3 * X[3].y;
            az = az * r + e0 * X[0].z + e1 * X[1].z + e2 * X[2].z + e3 * X[3].z;
            aw = aw * r + e0 * X[0].w + e1 * X[1].w + e2 * X[2].w + e3 * X[3].w;
            den = den * r + e0 + e1 + e2 + e3;
            m = mn;

#pragma unroll
            for (int u = 0; u < 4; u++) { A[u] = An[u]; Bv[u] = Bn[u]; }
        }
    }

    for (; j < end; j++) {
        float4 A = rec[2 * (size_t)j];
        float4 B = rec[2 * (size_t)j + 1];
        float4 X = *(const float4*)(g_xl + (size_t)__float_as_int(A.x) * HIDN + ch);
        float sp = edge_score(A, B, X);
#pragma unroll
        for (int off = 1; off <= 4; off <<= 1)
            sp += __shfl_xor_sync(0xffffffffu, sp, off);
        float mn = fmaxf(m, sp);
        float r  = __expf(m - mn);
        float wg = __expf(sp - mn);
        ax = ax * r + wg * X.x;
        ay = ay * r + wg * X.y;
        az = az * r + wg * X.z;
        aw = aw * r + wg * X.w;
        den = den * r + wg;
        m = mn;
    }

    float4 bc = *(const float4*)(bconv_l + ch);   // loaded late: fewer live regs in loop
    float inv = 1.0f / den;
    float4 o;
    o.x = ax * inv + bc.x;
    o.y = ay * inv + bc.y;
    o.z = az * inv + bc.z;
    o.w = aw * inv + bc.w;
    *(float4*)(g_conv + (size_t)node * HIDN + ch) = o;

    *(float4*)&s_sum[wid][ch] = o;
    *(float4*)&s_sq[wid][ch] = make_float4(o.x * o.x, o.y * o.y, o.z * o.z, o.w * o.w);
    __syncthreads();
    int t = threadIdx.x;
    if (t < HIDN) {
        float s = 0.f, q = 0.f;
#pragma unroll
        for (int w = 0; w < 8; w++) { s += s_sum[w][t]; q += s_sq[w][t]; }
        atomicAdd(&g_stats[l * 2 * HIDN + t], s);
        atomicAdd(&g_stats[l * 2 * HIDN + HIDN + t], q);
    }
}

// ---------------- final BN apply (layer 7) + residual + relu ----------------
__global__ void k_bnfinal(const float* __restrict__ gamma_l, const float* __restrict__ beta_l,
                          const float* __restrict__ res, float* __restrict__ out, int l) {
    int j4 = blockIdx.x * blockDim.x + threadIdx.x;
    if (j4 >= NN * HIDN / 4) return;
    int f4 = (j4 & 31);
    const float invN = 1.0f / (float)NN;

    float4 sum4 = ((const float4*)(g_stats + l * 2 * HIDN))[f4];
    float4 sq4  = ((const float4*)(g_stats + l * 2 * HIDN + HIDN))[f4];
    float4 gm = ((const float4*)gamma_l)[f4];
    float4 bt = ((const float4*)beta_l)[f4];
    float4 c = ((const float4*)g_conv)[j4];
    float4 r4 = ((const float4*)res)[j4];

    float4 y;
    float mean = sum4.x * invN, var = sq4.x * invN - mean * mean;
    y.x = gm.x * (c.x - mean) * rsqrtf(var + 1e-5f) + bt.x + r4.x;
    mean = sum4.y * invN; var = sq4.y * invN - mean * mean;
    y.y = gm.y * (c.y - mean) * rsqrtf(var + 1e-5f) + bt.y + r4.y;
    mean = sum4.z * invN; var = sq4.z * invN - mean * mean;
    y.z = gm.z * (c.z - mean) * rsqrtf(var + 1e-5f) + bt.z + r4.z;
    mean = sum4.w * invN; var = sq4.w * invN - mean * mean;
    y.w = gm.w * (c.w - mean) * rsqrtf(var + 1e-5f) + bt.w + r4.w;

    y.x = fmaxf(y.x, 0.f); y.y = fmaxf(y.y, 0.f);
    y.z = fmaxf(y.z, 0.f); y.w = fmaxf(y.w, 0.f);
    ((float4*)out)[j4] = y;
}

// ---------------- mean pooling per graph (run-accumulated, batch sorted) ----
__global__ void k_pool(const int* __restrict__ batch, const float* __restrict__ h) {
    int t = threadIdx.x;
    int f4 = t & 31;
    int grp = t >> 5;
    int n0 = (blockIdx.x * 8 + grp) * 8;
    float4 acc = make_float4(0.f, 0.f, 0.f, 0.f);
    float cnt = 0.f;
    int curb = __ldg(&batch[n0]);
#pragma unroll
    for (int k = 0; k < 8; k++) {
        int n = n0 + k;
        int b = __ldg(&batch[n]);
        if (b != curb) {
            atomicAdd(&g_pooled[curb * HIDN + f4 * 4 + 0], acc.x);
            atomicAdd(&g_pooled[curb * HIDN + f4 * 4 + 1], acc.y);
            atomicAdd(&g_pooled[curb * HIDN + f4 * 4 + 2], acc.z);
            atomicAdd(&g_pooled[curb * HIDN + f4 * 4 + 3], acc.w);
            if (f4 == 0) atomicAdd(&g_gcnt[curb], cnt);
            acc = make_float4(0.f, 0.f, 0.f, 0.f);
            cnt = 0.f;
            curb = b;
        }
        float4 v = ((const float4*)h)[n * 32 + f4];
        acc.x += v.x; acc.y += v.y; acc.z += v.z; acc.w += v.w;
        cnt += 1.f;
    }
    atomicAdd(&g_pooled[curb * HIDN + f4 * 4 + 0], acc.x);
    atomicAdd(&g_pooled[curb * HIDN + f4 * 4 + 1], acc.y);
    atomicAdd(&g_pooled[curb * HIDN + f4 * 4 + 2], acc.z);
    atomicAdd(&g_pooled[curb * HIDN + f4 * 4 + 3], acc.w);
    if (f4 == 0) atomicAdd(&g_gcnt[curb], cnt);
}

// ---------------- final MLP: relu(pooled@W1+b1)@W2+b2 ----------------------
__global__ void k_mlp(const float* __restrict__ W1, const float* __restrict__ b1,
                      const float* __restrict__ W2, const float* __restrict__ b2,
                      float* __restrict__ out) {
    __shared__ float pl[HIDN];
    __shared__ float hid[64];
    int g = blockIdx.x;
    int t = threadIdx.x;
    float inv = 1.0f / fmaxf(g_gcnt[g], 1.0f);
    for (int j = t; j < HIDN; j += 64) pl[j] = g_pooled[g * HIDN + j] * inv;
    __syncthreads();
    float a = b1[t];
    for (int k = 0; k < HIDN; k++) a += pl[k] * W1[k * 64 + t];
    hid[t] = fmaxf(a, 0.f);
    __syncthreads();
    if (t < 3) {
        float lg = b2[t];
        for (int k = 0; k < 64; k++) lg += hid[k] * W2[k * 3 + t];
        out[g * 3 + t] = lg;
    }
}

// ---------------- launch ----------------------------------------------------
extern "C" void kernel_launch(void* const* d_in, const int* in_sizes, int n_in,
                              void* d_out, int out_size) {
    const float* x     = (const float*)d_in[0];
    const int*   ei    = (const int*)d_in[1];
    const float* ea    = (const float*)d_in[2];
    const int*   batch = (const int*)d_in[3];
    const float* Win   = (const float*)d_in[4];
    const float* b_in  = (const float*)d_in[5];
    const float* Wl    = (const float*)d_in[6];
    const float* bl    = (const float*)d_in[7];
    const float* Wr    = (const float*)d_in[8];
    const float* br    = (const float*)d_in[9];
    const float* We    = (const float*)d_in[10];
    const float* att   = (const float*)d_in[11];
    const float* bconv = (const float*)d_in[12];
    const float* gamma = (const float*)d_in[13];
    const float* beta  = (const float*)d_in[14];
    const float* W1    = (const float*)d_in[15];
    const float* b1    = (const float*)d_in[16];
    const float* W2    = (const float*)d_in[17];
    const float* b2    = (const float*)d_in[18];
    float* out = (float*)d_out;

    float *bufA = nullptr, *bufB = nullptr, *convp = nullptr, *statsp = nullptr;
    cudaGetSymbolAddress((void**)&bufA, g_bufA);
    cudaGetSymbolAddress((void**)&bufB, g_bufB);
    cudaGetSymbolAddress((void**)&convp, g_conv);
    cudaGetSymbolAddress((void**)&statsp, g_stats);
    __nv_bfloat16* whi = nullptr;
    __nv_bfloat16* wlo = nullptr;
    cudaGetSymbolAddress((void**)&whi, g_w_hi);
    cudaGetSymbolAddress((void**)&wlo, g_w_lo);

    k_init<<<64, 256>>>();
    k_wsplit<<<(NLAY * 2 * HIDN * HIDN + 255) / 256, 256>>>(Wl, Wr);
    k_deg<<<(EE + 255) / 256, 256>>>(ei);
    k_scanA<<<64, 256>>>();
    k_scanB<<<1, 192>>>();
    k_scanC<<<64, 256>>>();
    k_scatter<<<(EF + 255) / 256, 256>>>(ei, ea);
    k_loopattr<<<NN / 8, 256>>>();
    k_ingemm<<<NN, HIDN>>>(x, Win, b_in);

    dim3 ggrid(NN / 128, 2);
    for (int l = 0; l < NLAY; l++) {
        const float* conv_src = (l == 0) ? bufA : convp;
        const float* st = (l == 0) ? nullptr : statsp + (size_t)(l - 1) * 2 * HIDN;
        const float* gm = (l == 0) ? nullptr : gamma + (size_t)(l - 1) * HIDN;
        const float* bt = (l == 0) ? nullptr : beta + (size_t)(l - 1) * HIDN;
        const float* res = nullptr;
        float* hout = nullptr;
        if (l == 2) { res = bufA; hout = bufB; }
        if (l == 4) { res = bufB; hout = bufA; }
        if (l == 6) { res = bufA; hout = bufB; }

        k_gemm_bf16<<<ggrid, 256>>>(whi + (size_t)l * 2 * HIDN * HIDN,
                                    wlo + (size_t)l * 2 * HIDN * HIDN,
                                    bl + (size_t)l * HIDN, br + (size_t)l * HIDN,
                                    conv_src, st, gm, bt, res, hout);
        k_fused<<<NN / 8, 256>>>(We + (size_t)l * EDIM * HIDN,
                                 att + (size_t)l * NHEAD * HC,
                                 bconv + (size_t)l * HIDN, l);
    }

    k_bnfinal<<<NN * HIDN / 4 / 256, 256>>>(gamma + 7 * HIDN, beta + 7 * HIDN,
                                            bufB, bufA, 7);
    k_pool<<<NN / 64, 256>>>(batch, bufA);
    k_mlp<<<GG, 64>>>(W1, b1, W2, b2, out);
}